// round 10
// baseline (speedup 1.0000x reference)
#include <cuda_runtime.h>
#include <cuda_bf16.h>
#include <cuda_fp16.h>
#include <cuda_fp8.h>
#include <cstdint>
#include <math.h>

// ---------------------------------------------------------------------------
// out[M, 2048] = x[M, 2048] @ w[2048, 2048]^T + bias
// Harness transports all tensors as float32 (bf16/fp8 values upcast).
// ---------------------------------------------------------------------------
#define IN_DIM  2048
#define OUT_DIM 2048
#define MROWS   32768
#define BM 128
#define BN 128
#define BK 64
#define STAGES 4
#define KT (IN_DIM / BK)     // 32
#define THREADS 256

// Padded shared layout: row stride 72 bf16 = 144 bytes (16B aligned,
// conflict-free for cp.async stores and fragment LDS reads).
#define RS 72
#define TILE_E (128 * RS)
#define STAGE_E (2 * TILE_E)
#define SMEM_TOTAL (STAGES * STAGE_E * 2)   // 147456 bytes

__device__ __forceinline__ void cp_async16(uint32_t dst, const void* src) {
    asm volatile("cp.async.cg.shared.global [%0], [%1], 16;" :: "r"(dst), "l"(src));
}

__device__ __forceinline__ uint32_t smem_u32(const void* p) {
    uint32_t a;
    asm("{ .reg .u64 t; cvta.to.shared.u64 t, %1; cvt.u32.u64 %0, t; }" : "=r"(a) : "l"(p));
    return a;
}

__device__ __forceinline__ void mma_bf16(float* d, const uint32_t* a, const uint32_t* b) {
    asm volatile(
        "mma.sync.aligned.m16n8k16.row.col.f32.bf16.bf16.f32 "
        "{%0,%1,%2,%3}, {%4,%5,%6,%7}, {%8,%9}, {%0,%1,%2,%3};"
        : "+f"(d[0]), "+f"(d[1]), "+f"(d[2]), "+f"(d[3])
        : "r"(a[0]), "r"(a[1]), "r"(a[2]), "r"(a[3]), "r"(b[0]), "r"(b[1]));
}

// ---------------------------------------------------------------------------
// Static scratch (bss; allocation-free rule)
// ---------------------------------------------------------------------------
__device__ __align__(1024) __nv_bfloat16 g_wbf[(size_t)OUT_DIM * IN_DIM];   // 8 MB
__device__ __align__(1024) __nv_bfloat16 g_xbf[(size_t)MROWS * IN_DIM];     // 128 MB
__device__ int g_wmode;  // 0 raw fp8 bytes | 1 bf16 vals | 2 f32 vals (expected)
                         // 3 f32 bitpattern | 4 bf16 bitpattern | 5 int32 byte
__device__ int g_xmode;  // 0 = bf16 array | 1 = f32 array (expected)

// ---------------------------------------------------------------------------
// Probe. Weight: structure + existence tests (1024 samples).
// x: decisive zero-low-half test — f32 storage of bf16 values has
// (word & 0xFFFF)==0 for EVERY word; a true bf16 array almost never does.
// ---------------------------------------------------------------------------
__global__ void probe_kernel(const uint32_t* __restrict__ w,
                             const uint32_t* __restrict__ x) {
    __shared__ int c_i32, c_low16, c_f32bad, c_nib, c_halfint, c_mant, c_xlow;
    int t = threadIdx.x;
    if (t == 0) { c_i32 = 0; c_low16 = 0; c_f32bad = 0; c_nib = 0; c_halfint = 0; c_mant = 0; c_xlow = 0; }
    __syncthreads();

    // ---- weight sample (stays within the smallest candidate footprint)
    uint32_t v = w[t * 1024 + 37];
    uint32_t hi24 = v >> 8;
    if (hi24 == 0u || hi24 == 0xFFFFFFu) atomicAdd(&c_i32, 1);
    if ((v & 0xFFFFu) == 0) atomicAdd(&c_low16, 1);
    {
        float f = __uint_as_float(v);
        bool bad = !isfinite(f) || f != rintf(f) || fabsf(f) > 255.5f;
        if (bad) atomicAdd(&c_f32bad, 1);   // exists only for VALUE storage
    }
    if ((v & 0x000F000Fu) == 0) atomicAdd(&c_nib, 1);
    {
        float h0 = __bfloat162float(__ushort_as_bfloat16((unsigned short)(v & 0xFFFF)));
        float h1 = __bfloat162float(__ushort_as_bfloat16((unsigned short)(v >> 16)));
        bool i0 = isfinite(h0) && h0 == rintf(h0) && fabsf(h0) <= 255.5f;
        bool i1 = isfinite(h1) && h1 == rintf(h1) && fabsf(h1) <= 255.5f;
        if (!(i0 && i1)) atomicAdd(&c_halfint, 1);  // exists only for VALUE storage
    }
    if ((v & 0x00700070u) != 0) atomicAdd(&c_mant, 1);

    // ---- x sample (stride keeps within a bf16-sized buffer too)
    uint32_t vx = x[t * 32768 + 11];
    if ((vx & 0xFFFFu) == 0) atomicAdd(&c_xlow, 1);

    __syncthreads();
    if (t == 0) {
        int wm;
        if (c_i32 >= 1000) wm = 5;
        else if (c_low16 >= 1000) wm = (c_f32bad >= 16) ? 2 : 3;
        else if (c_nib >= 1000) {
            if (c_halfint >= 16) wm = 1;        // bf16 VALUES (non-int/large exist)
            else wm = 4;                         // bf16 of bitpattern ints
        } else wm = 0;                           // raw fp8 bytes
        g_wmode = wm;
        g_xmode = (c_xlow >= 512) ? 1 : 0;       // f32-of-bf16: 1024; bf16: ~0
    }
}

// ---------------------------------------------------------------------------
// x conversion: f32-stored x -> bf16 scratch (exact: values are bf16-valued)
// ---------------------------------------------------------------------------
__global__ void xconv_kernel(const float* __restrict__ xf) {
    if (!g_xmode) return;
    size_t i = ((size_t)blockIdx.x * blockDim.x + threadIdx.x) * 4;
    float4 f = *reinterpret_cast<const float4*>(xf + i);
    __nv_bfloat16 o[4] = {__float2bfloat16(f.x), __float2bfloat16(f.y),
                          __float2bfloat16(f.z), __float2bfloat16(f.w)};
    *reinterpret_cast<uint2*>(g_xbf + i) = *reinterpret_cast<const uint2*>(o);
}

// ---------------------------------------------------------------------------
// Dequant: storage mode -> bf16(e4m3_value) * bf16(scale)  (reference math)
// ---------------------------------------------------------------------------
__device__ __forceinline__ __nv_bfloat16 e4m3_to_bf16(uint8_t byte) {
    __nv_fp8_e4m3 f8;
    f8.__x = byte;
    return __float2bfloat16((float)f8);  // exact
}

__global__ void dequant_kernel(const void* __restrict__ wraw, const float* __restrict__ scale) {
    size_t i = ((size_t)blockIdx.x * blockDim.x + threadIdx.x) * 8;
    __nv_bfloat16 sb = __float2bfloat16(*scale);
    int mode = g_wmode;
    __nv_bfloat16 o[8];

    if (mode == 2 || mode == 3) {                 // f32 storage (mode 2 expected)
        const float4* p = reinterpret_cast<const float4*>((const float*)wraw + i);
        float4 f0 = p[0], f1 = p[1];
        float f[8] = {f0.x, f0.y, f0.z, f0.w, f1.x, f1.y, f1.z, f1.w};
#pragma unroll
        for (int b = 0; b < 8; b++) {
            if (mode == 2) o[b] = __hmul(__float2bfloat16(f[b]), sb);
            else o[b] = __hmul(e4m3_to_bf16((uint8_t)(((int)lrintf(f[b])) & 0xFF)), sb);
        }
    } else if (mode == 1 || mode == 4) {          // bf16 storage
        uint4 raw = *reinterpret_cast<const uint4*>((const __nv_bfloat16*)wraw + i);
        const __nv_bfloat16* wb = reinterpret_cast<const __nv_bfloat16*>(&raw);
#pragma unroll
        for (int b = 0; b < 8; b++) {
            if (mode == 1) o[b] = __hmul(wb[b], sb);
            else o[b] = __hmul(e4m3_to_bf16((uint8_t)(((int)lrintf(__bfloat162float(wb[b]))) & 0xFF)), sb);
        }
    } else if (mode == 5) {                       // int32 of byte
        const int4* p = reinterpret_cast<const int4*>((const int*)wraw + i);
        int4 v0 = p[0], v1 = p[1];
        int vi[8] = {v0.x, v0.y, v0.z, v0.w, v1.x, v1.y, v1.z, v1.w};
#pragma unroll
        for (int b = 0; b < 8; b++)
            o[b] = __hmul(e4m3_to_bf16((uint8_t)(vi[b] & 0xFF)), sb);
    } else {                                      // raw fp8 bytes
        uint2 raw = *reinterpret_cast<const uint2*>((const uint8_t*)wraw + i);
        uint32_t words[2] = {raw.x, raw.y};
#pragma unroll
        for (int b = 0; b < 8; b++)
            o[b] = __hmul(e4m3_to_bf16((words[b >> 2] >> ((b & 3) * 8)) & 0xFF), sb);
    }
    *reinterpret_cast<uint4*>(g_wbf + i) = *reinterpret_cast<const uint4*>(o);
}

// ---------------------------------------------------------------------------
// Multistage mma.sync GEMM. CTA 128x128, BK=64, 4-stage cp.async pipeline.
// A-source and output dtype selected device-side by g_xmode.
// ---------------------------------------------------------------------------
__global__ void __launch_bounds__(THREADS, 1)
gemm_kernel(const __nv_bfloat16* __restrict__ x,
            const void* __restrict__ bias,
            void* __restrict__ outv) {
    extern __shared__ __nv_bfloat16 sm[];
    uint32_t sb = smem_u32(sm);

    int xmode = g_xmode;
    const __nv_bfloat16* xsrc = xmode ? g_xbf : x;

    int tid = threadIdx.x;
    int lane = tid & 31;
    int wid = tid >> 5;
    int gid = lane >> 2;
    int tig = lane & 3;
    int warp_m = (wid & 3) * 32;
    int warp_n = (wid >> 2) * 64;
    int m0 = blockIdx.y * BM;
    int n0 = blockIdx.x * BN;

    int lrow = tid >> 3;
    int lseg = tid & 7;
    const __nv_bfloat16* gA = xsrc + (size_t)(m0 + lrow) * IN_DIM + lseg * 8;
    const __nv_bfloat16* gB = g_wbf + (size_t)(n0 + lrow) * IN_DIM + lseg * 8;

    auto load_stage = [&](int stage, int kchunk) {
        const __nv_bfloat16* a = gA + kchunk * BK;
        const __nv_bfloat16* b = gB + kchunk * BK;
#pragma unroll
        for (int w = 0; w < 4; w++) {
            int row = lrow + w * 32;
            uint32_t adst = sb + (uint32_t)(stage * STAGE_E + row * RS) * 2 + lseg * 16;
            uint32_t bdst = sb + (uint32_t)(stage * STAGE_E + TILE_E + row * RS) * 2 + lseg * 16;
            cp_async16(adst, a + (size_t)w * 32 * IN_DIM);
            cp_async16(bdst, b + (size_t)w * 32 * IN_DIM);
        }
    };

#pragma unroll
    for (int s = 0; s < STAGES - 1; s++) {
        load_stage(s, s);
        asm volatile("cp.async.commit_group;" ::: "memory");
    }

    float acc[2][8][4] = {};

#pragma unroll 1
    for (int it = 0; it < KT; it++) {
        asm volatile("cp.async.wait_group 2;" ::: "memory");
        __syncthreads();
        if (it + STAGES - 1 < KT) load_stage((it + STAGES - 1) & (STAGES - 1), it + STAGES - 1);
        asm volatile("cp.async.commit_group;" ::: "memory");

        int aBase = (it & (STAGES - 1)) * STAGE_E;
        int bBase = aBase + TILE_E;

#pragma unroll
        for (int ks = 0; ks < 4; ks++) {
            int kb = ks * 16 + 2 * tig;

            uint32_t a_regs[2][4];
#pragma unroll
            for (int mt = 0; mt < 2; mt++) {
                int r0 = warp_m + mt * 16 + gid;
                const __nv_bfloat16* ap = sm + aBase + r0 * RS + kb;
                a_regs[mt][0] = *reinterpret_cast<const uint32_t*>(ap);
                a_regs[mt][1] = *reinterpret_cast<const uint32_t*>(ap + 8 * RS);
                a_regs[mt][2] = *reinterpret_cast<const uint32_t*>(ap + 8);
                a_regs[mt][3] = *reinterpret_cast<const uint32_t*>(ap + 8 * RS + 8);
            }
            uint32_t b_regs[8][2];
#pragma unroll
            for (int nt = 0; nt < 8; nt++) {
                int nr = warp_n + nt * 8 + gid;
                const __nv_bfloat16* bp = sm + bBase + nr * RS + kb;
                b_regs[nt][0] = *reinterpret_cast<const uint32_t*>(bp);
                b_regs[nt][1] = *reinterpret_cast<const uint32_t*>(bp + 8);
            }
#pragma unroll
            for (int mt = 0; mt < 2; mt++)
#pragma unroll
                for (int nt = 0; nt < 8; nt++)
                    mma_bf16(acc[mt][nt], a_regs[mt], b_regs[nt]);
        }
    }

    // epilogue: bf16(acc) + bf16(bias), then store in the transport dtype.
    int rbase = m0 + warp_m + gid;
    int cbase = n0 + warp_n + tig * 2;
#pragma unroll
    for (int mt = 0; mt < 2; mt++) {
#pragma unroll
        for (int nt = 0; nt < 8; nt++) {
            int c = cbase + nt * 8;
            int r0 = rbase + mt * 16;
            __nv_bfloat16 bx, by;
            if (xmode) {
                float2 bi = *reinterpret_cast<const float2*>((const float*)bias + c);
                bx = __float2bfloat16(bi.x);
                by = __float2bfloat16(bi.y);
            } else {
                __nv_bfloat162 bi = *reinterpret_cast<const __nv_bfloat162*>((const __nv_bfloat16*)bias + c);
                bx = bi.x;
                by = bi.y;
            }
            __nv_bfloat16 v00 = __hadd(__float2bfloat16(acc[mt][nt][0]), bx);
            __nv_bfloat16 v01 = __hadd(__float2bfloat16(acc[mt][nt][1]), by);
            __nv_bfloat16 v10 = __hadd(__float2bfloat16(acc[mt][nt][2]), bx);
            __nv_bfloat16 v11 = __hadd(__float2bfloat16(acc[mt][nt][3]), by);
            if (xmode) {
                float* of = (float*)outv;
                float2 q0 = {__bfloat162float(v00), __bfloat162float(v01)};
                float2 q1 = {__bfloat162float(v10), __bfloat162float(v11)};
                *reinterpret_cast<float2*>(of + (size_t)r0 * OUT_DIM + c) = q0;
                *reinterpret_cast<float2*>(of + (size_t)(r0 + 8) * OUT_DIM + c) = q1;
            } else {
                __nv_bfloat16* ob = (__nv_bfloat16*)outv;
                __nv_bfloat162 q0 = {v00, v01};
                __nv_bfloat162 q1 = {v10, v11};
                *reinterpret_cast<__nv_bfloat162*>(ob + (size_t)r0 * OUT_DIM + c) = q0;
                *reinterpret_cast<__nv_bfloat162*>(ob + (size_t)(r0 + 8) * OUT_DIM + c) = q1;
            }
        }
    }
}

// ---------------------------------------------------------------------------
// Host launch. Identification by element count (ordering-proof):
//   x == out_size, weight 4194304, bias 2048, scale 1.
// ---------------------------------------------------------------------------
extern "C" void kernel_launch(void* const* d_in, const int* in_sizes, int n_in,
                              void* d_out, int out_size) {
    const void* x = nullptr;
    const void* w = nullptr;
    const float* scale = nullptr;
    const void* bias = nullptr;

    for (int i = 0; i < n_in; i++) {
        long long sz = in_sizes[i];
        if (sz == 1 && !scale) scale = (const float*)d_in[i];
        else if (sz == OUT_DIM && !bias) bias = d_in[i];
        else if (sz == (long long)OUT_DIM * IN_DIM && !w) w = d_in[i];
        else if (sz == (long long)out_size && !x) x = d_in[i];
    }

    int M = out_size / OUT_DIM;  // 32768

    probe_kernel<<<1, 1024>>>((const uint32_t*)w, (const uint32_t*)x);
    xconv_kernel<<<(unsigned)((size_t)M * IN_DIM / 4 / 256), 256>>>((const float*)x);
    dequant_kernel<<<(OUT_DIM * IN_DIM / 8) / 256, 256>>>(w, scale);

    cudaFuncSetAttribute(gemm_kernel, cudaFuncAttributeMaxDynamicSharedMemorySize, SMEM_TOTAL);
    dim3 grid(OUT_DIM / BN, (unsigned)(M / BM));  // (16, 256)
    gemm_kernel<<<grid, THREADS, SMEM_TOTAL>>>((const __nv_bfloat16*)x, bias, d_out);
}

// round 11
// speedup vs baseline: 1.1931x; 1.1931x over previous
#include <cuda_runtime.h>
#include <cuda_bf16.h>
#include <cuda_fp16.h>
#include <cuda_fp8.h>
#include <cstdint>
#include <math.h>

// ---------------------------------------------------------------------------
// out[M, 2048] = x[M, 2048] @ w[2048, 2048]^T + bias
// Harness transports all tensors as float32 (bf16/fp8 values upcast).
// ---------------------------------------------------------------------------
#define IN_DIM  2048
#define OUT_DIM 2048
#define MROWS   32768
#define BM 128
#define BN 128
#define BK 64
#define STAGES 3
#define KT (IN_DIM / BK)     // 32
#define THREADS 256

// Padded shared layout: row stride 72 bf16 = 144 bytes. 16B-aligned for
// cp.async; 8 rows x 16B ldmatrix phases cover all 32 banks exactly once.
#define RS 72
#define RSB (RS * 2)                       // 144 bytes
#define TILE_E (128 * RS)
#define STAGE_E (2 * TILE_E)
#define SMEM_TOTAL (STAGES * STAGE_E * 2)  // 110592 bytes -> 2 CTAs/SM

__device__ __forceinline__ void cp_async16(uint32_t dst, const void* src) {
    asm volatile("cp.async.cg.shared.global [%0], [%1], 16;" :: "r"(dst), "l"(src));
}

__device__ __forceinline__ uint32_t smem_u32(const void* p) {
    uint32_t a;
    asm("{ .reg .u64 t; cvta.to.shared.u64 t, %1; cvt.u32.u64 %0, t; }" : "=r"(a) : "l"(p));
    return a;
}

__device__ __forceinline__ void ldmatrix_x4(uint32_t* r, uint32_t addr) {
    asm volatile("ldmatrix.sync.aligned.m8n8.x4.shared.b16 {%0,%1,%2,%3}, [%4];"
                 : "=r"(r[0]), "=r"(r[1]), "=r"(r[2]), "=r"(r[3]) : "r"(addr));
}

__device__ __forceinline__ void mma_bf16(float* d, const uint32_t* a, const uint32_t* b) {
    asm volatile(
        "mma.sync.aligned.m16n8k16.row.col.f32.bf16.bf16.f32 "
        "{%0,%1,%2,%3}, {%4,%5,%6,%7}, {%8,%9}, {%0,%1,%2,%3};"
        : "+f"(d[0]), "+f"(d[1]), "+f"(d[2]), "+f"(d[3])
        : "r"(a[0]), "r"(a[1]), "r"(a[2]), "r"(a[3]), "r"(b[0]), "r"(b[1]));
}

// ---------------------------------------------------------------------------
// Static scratch (bss; allocation-free rule)
// ---------------------------------------------------------------------------
__device__ __align__(1024) __nv_bfloat16 g_wbf[(size_t)OUT_DIM * IN_DIM];   // 8 MB
__device__ __align__(1024) __nv_bfloat16 g_xbf[(size_t)MROWS * IN_DIM];     // 128 MB
__device__ int g_wmode;  // 0 raw fp8 | 1 bf16 vals | 2 f32 vals (expected)
                         // 3 f32 bitpattern | 4 bf16 bitpattern | 5 int32 byte
__device__ int g_xmode;  // 0 = bf16 array | 1 = f32 array (expected)

// ---------------------------------------------------------------------------
// Probe (proven in R10): weight structure + existence tests; x zero-low-half.
// ---------------------------------------------------------------------------
__global__ void probe_kernel(const uint32_t* __restrict__ w,
                             const uint32_t* __restrict__ x) {
    __shared__ int c_i32, c_low16, c_f32bad, c_nib, c_halfint, c_xlow;
    int t = threadIdx.x;
    if (t == 0) { c_i32 = 0; c_low16 = 0; c_f32bad = 0; c_nib = 0; c_halfint = 0; c_xlow = 0; }
    __syncthreads();

    uint32_t v = w[t * 1024 + 37];
    uint32_t hi24 = v >> 8;
    if (hi24 == 0u || hi24 == 0xFFFFFFu) atomicAdd(&c_i32, 1);
    if ((v & 0xFFFFu) == 0) atomicAdd(&c_low16, 1);
    {
        float f = __uint_as_float(v);
        bool bad = !isfinite(f) || f != rintf(f) || fabsf(f) > 255.5f;
        if (bad) atomicAdd(&c_f32bad, 1);
    }
    if ((v & 0x000F000Fu) == 0) atomicAdd(&c_nib, 1);
    {
        float h0 = __bfloat162float(__ushort_as_bfloat16((unsigned short)(v & 0xFFFF)));
        float h1 = __bfloat162float(__ushort_as_bfloat16((unsigned short)(v >> 16)));
        bool i0 = isfinite(h0) && h0 == rintf(h0) && fabsf(h0) <= 255.5f;
        bool i1 = isfinite(h1) && h1 == rintf(h1) && fabsf(h1) <= 255.5f;
        if (!(i0 && i1)) atomicAdd(&c_halfint, 1);
    }

    uint32_t vx = x[t * 32768 + 11];
    if ((vx & 0xFFFFu) == 0) atomicAdd(&c_xlow, 1);

    __syncthreads();
    if (t == 0) {
        int wm;
        if (c_i32 >= 1000) wm = 5;
        else if (c_low16 >= 1000) wm = (c_f32bad >= 16) ? 2 : 3;
        else if (c_nib >= 1000) wm = (c_halfint >= 16) ? 1 : 4;
        else wm = 0;
        g_wmode = wm;
        g_xmode = (c_xlow >= 512) ? 1 : 0;
    }
}

// ---------------------------------------------------------------------------
// x conversion: f32-stored x -> bf16 scratch (exact; values are bf16-valued)
// ---------------------------------------------------------------------------
__global__ void xconv_kernel(const float* __restrict__ xf) {
    if (!g_xmode) return;
    size_t i = ((size_t)blockIdx.x * blockDim.x + threadIdx.x) * 4;
    float4 f = *reinterpret_cast<const float4*>(xf + i);
    __nv_bfloat16 o[4] = {__float2bfloat16(f.x), __float2bfloat16(f.y),
                          __float2bfloat16(f.z), __float2bfloat16(f.w)};
    *reinterpret_cast<uint2*>(g_xbf + i) = *reinterpret_cast<const uint2*>(o);
}

// ---------------------------------------------------------------------------
// Dequant: storage mode -> bf16(e4m3_value) * bf16(scale)  (reference math)
// ---------------------------------------------------------------------------
__device__ __forceinline__ __nv_bfloat16 e4m3_to_bf16(uint8_t byte) {
    __nv_fp8_e4m3 f8;
    f8.__x = byte;
    return __float2bfloat16((float)f8);  // exact
}

__global__ void dequant_kernel(const void* __restrict__ wraw, const float* __restrict__ scale) {
    size_t i = ((size_t)blockIdx.x * blockDim.x + threadIdx.x) * 8;
    __nv_bfloat16 sb = __float2bfloat16(*scale);
    int mode = g_wmode;
    __nv_bfloat16 o[8];

    if (mode == 2 || mode == 3) {
        const float4* p = reinterpret_cast<const float4*>((const float*)wraw + i);
        float4 f0 = p[0], f1 = p[1];
        float f[8] = {f0.x, f0.y, f0.z, f0.w, f1.x, f1.y, f1.z, f1.w};
#pragma unroll
        for (int b = 0; b < 8; b++) {
            if (mode == 2) o[b] = __hmul(__float2bfloat16(f[b]), sb);
            else o[b] = __hmul(e4m3_to_bf16((uint8_t)(((int)lrintf(f[b])) & 0xFF)), sb);
        }
    } else if (mode == 1 || mode == 4) {
        uint4 raw = *reinterpret_cast<const uint4*>((const __nv_bfloat16*)wraw + i);
        const __nv_bfloat16* wb = reinterpret_cast<const __nv_bfloat16*>(&raw);
#pragma unroll
        for (int b = 0; b < 8; b++) {
            if (mode == 1) o[b] = __hmul(wb[b], sb);
            else o[b] = __hmul(e4m3_to_bf16((uint8_t)(((int)lrintf(__bfloat162float(wb[b]))) & 0xFF)), sb);
        }
    } else if (mode == 5) {
        const int4* p = reinterpret_cast<const int4*>((const int*)wraw + i);
        int4 v0 = p[0], v1 = p[1];
        int vi[8] = {v0.x, v0.y, v0.z, v0.w, v1.x, v1.y, v1.z, v1.w};
#pragma unroll
        for (int b = 0; b < 8; b++)
            o[b] = __hmul(e4m3_to_bf16((uint8_t)(vi[b] & 0xFF)), sb);
    } else {
        uint2 raw = *reinterpret_cast<const uint2*>((const uint8_t*)wraw + i);
        uint32_t words[2] = {raw.x, raw.y};
#pragma unroll
        for (int b = 0; b < 8; b++)
            o[b] = __hmul(e4m3_to_bf16((words[b >> 2] >> ((b & 3) * 8)) & 0xFF), sb);
    }
    *reinterpret_cast<uint4*>(g_wbf + i) = *reinterpret_cast<const uint4*>(o);
}

// ---------------------------------------------------------------------------
// Multistage mma.sync GEMM. CTA 128x128, BK=64, 3-stage cp.async pipeline,
// 2 CTAs/SM, ldmatrix.x4 fragment loads (mapping == proven LDS version).
// ---------------------------------------------------------------------------
__global__ void __launch_bounds__(THREADS, 2)
gemm_kernel(const __nv_bfloat16* __restrict__ x,
            const void* __restrict__ bias,
            void* __restrict__ outv) {
    extern __shared__ __nv_bfloat16 sm[];
    uint32_t sb = smem_u32(sm);

    int xmode = g_xmode;
    const __nv_bfloat16* xsrc = xmode ? g_xbf : x;

    int tid = threadIdx.x;
    int lane = tid & 31;
    int wid = tid >> 5;
    int gid = lane >> 2;
    int tig = lane & 3;
    int warp_m = (wid & 3) * 32;
    int warp_n = (wid >> 2) * 64;
    int m0 = blockIdx.y * BM;
    int n0 = blockIdx.x * BN;

    int lrow = tid >> 3;
    int lseg = tid & 7;
    const __nv_bfloat16* gA = xsrc + (size_t)(m0 + lrow) * IN_DIM + lseg * 8;
    const __nv_bfloat16* gB = g_wbf + (size_t)(n0 + lrow) * IN_DIM + lseg * 8;

    auto load_stage = [&](int stage, int kchunk) {
        const __nv_bfloat16* a = gA + kchunk * BK;
        const __nv_bfloat16* b = gB + kchunk * BK;
#pragma unroll
        for (int w = 0; w < 4; w++) {
            int row = lrow + w * 32;
            uint32_t adst = sb + (uint32_t)(stage * STAGE_E + row * RS) * 2 + lseg * 16;
            uint32_t bdst = sb + (uint32_t)(stage * STAGE_E + TILE_E + row * RS) * 2 + lseg * 16;
            cp_async16(adst, a + (size_t)w * 32 * IN_DIM);
            cp_async16(bdst, b + (size_t)w * 32 * IN_DIM);
        }
    };

#pragma unroll
    for (int s = 0; s < STAGES - 1; s++) {
        load_stage(s, s);
        asm volatile("cp.async.commit_group;" ::: "memory");
    }

    float acc[2][8][4] = {};

    // ldmatrix per-lane base offsets (bytes), derived to reproduce the proven
    // LDS fragment mapping exactly:
    //  A tiles r0..r3 = (rows0-7,k0-7)(rows8-15,k0-7)(rows0-7,k8-15)(rows8-15,k8-15)
    //    lane addr: row = warp_m + (lane&15), +16B if lane>=16
    //  B tiles r0..r3 = (n0-7,k0-7)(n0-7,k8-15)(n8-15,k0-7)(n8-15,k8-15)
    //    lane addr: n = warp_n + ((lane>>4)&1)*8 + (lane&7), k += ((lane>>3)&1)*8
    uint32_t a_loff = (uint32_t)(warp_m + (lane & 15)) * RSB + (lane >> 4) * 16;
    uint32_t b_loff = (uint32_t)(warp_n + ((lane >> 4) & 1) * 8 + (lane & 7)) * RSB
                      + ((lane >> 3) & 1) * 16;

#pragma unroll 1
    for (int it = 0; it < KT; it++) {
        asm volatile("cp.async.wait_group 1;" ::: "memory");
        __syncthreads();
        if (it + STAGES - 1 < KT) load_stage((it + STAGES - 1) % STAGES, it + STAGES - 1);
        asm volatile("cp.async.commit_group;" ::: "memory");

        uint32_t aBase = sb + (uint32_t)((it % STAGES) * STAGE_E) * 2;
        uint32_t bBase = aBase + TILE_E * 2;

#pragma unroll
        for (int ks = 0; ks < 4; ks++) {
            uint32_t kbyte = ks * 32;

            uint32_t a_regs[2][4];
#pragma unroll
            for (int mt = 0; mt < 2; mt++)
                ldmatrix_x4(a_regs[mt], aBase + a_loff + (uint32_t)mt * 16 * RSB + kbyte);

            uint32_t b_regs[8][2];
#pragma unroll
            for (int np = 0; np < 4; np++) {
                uint32_t t4[4];
                ldmatrix_x4(t4, bBase + b_loff + (uint32_t)np * 16 * RSB + kbyte);
                b_regs[np * 2][0] = t4[0];
                b_regs[np * 2][1] = t4[1];
                b_regs[np * 2 + 1][0] = t4[2];
                b_regs[np * 2 + 1][1] = t4[3];
            }
#pragma unroll
            for (int mt = 0; mt < 2; mt++)
#pragma unroll
                for (int nt = 0; nt < 8; nt++)
                    mma_bf16(acc[mt][nt], a_regs[mt], b_regs[nt]);
        }
    }

    // epilogue: bf16(acc) + bf16(bias), stored in transport dtype
    int rbase = m0 + warp_m + gid;
    int cbase = n0 + warp_n + tig * 2;
#pragma unroll
    for (int mt = 0; mt < 2; mt++) {
#pragma unroll
        for (int nt = 0; nt < 8; nt++) {
            int c = cbase + nt * 8;
            int r0 = rbase + mt * 16;
            __nv_bfloat16 bx, by;
            if (xmode) {
                float2 bi = *reinterpret_cast<const float2*>((const float*)bias + c);
                bx = __float2bfloat16(bi.x);
                by = __float2bfloat16(bi.y);
            } else {
                __nv_bfloat162 bi = *reinterpret_cast<const __nv_bfloat162*>((const __nv_bfloat16*)bias + c);
                bx = bi.x;
                by = bi.y;
            }
            __nv_bfloat16 v00 = __hadd(__float2bfloat16(acc[mt][nt][0]), bx);
            __nv_bfloat16 v01 = __hadd(__float2bfloat16(acc[mt][nt][1]), by);
            __nv_bfloat16 v10 = __hadd(__float2bfloat16(acc[mt][nt][2]), bx);
            __nv_bfloat16 v11 = __hadd(__float2bfloat16(acc[mt][nt][3]), by);
            if (xmode) {
                float* of = (float*)outv;
                float2 q0 = {__bfloat162float(v00), __bfloat162float(v01)};
                float2 q1 = {__bfloat162float(v10), __bfloat162float(v11)};
                *reinterpret_cast<float2*>(of + (size_t)r0 * OUT_DIM + c) = q0;
                *reinterpret_cast<float2*>(of + (size_t)(r0 + 8) * OUT_DIM + c) = q1;
            } else {
                __nv_bfloat16* ob = (__nv_bfloat16*)outv;
                __nv_bfloat162 q0 = {v00, v01};
                __nv_bfloat162 q1 = {v10, v11};
                *reinterpret_cast<__nv_bfloat162*>(ob + (size_t)r0 * OUT_DIM + c) = q0;
                *reinterpret_cast<__nv_bfloat162*>(ob + (size_t)(r0 + 8) * OUT_DIM + c) = q1;
            }
        }
    }
}

// ---------------------------------------------------------------------------
// Host launch. Identification by element count (ordering-proof).
// ---------------------------------------------------------------------------
extern "C" void kernel_launch(void* const* d_in, const int* in_sizes, int n_in,
                              void* d_out, int out_size) {
    const void* x = nullptr;
    const void* w = nullptr;
    const float* scale = nullptr;
    const void* bias = nullptr;

    for (int i = 0; i < n_in; i++) {
        long long sz = in_sizes[i];
        if (sz == 1 && !scale) scale = (const float*)d_in[i];
        else if (sz == OUT_DIM && !bias) bias = d_in[i];
        else if (sz == (long long)OUT_DIM * IN_DIM && !w) w = d_in[i];
        else if (sz == (long long)out_size && !x) x = d_in[i];
    }

    int M = out_size / OUT_DIM;  // 32768

    probe_kernel<<<1, 1024>>>((const uint32_t*)w, (const uint32_t*)x);
    xconv_kernel<<<(unsigned)((size_t)M * IN_DIM / 4 / 256), 256>>>((const float*)x);
    dequant_kernel<<<(OUT_DIM * IN_DIM / 8) / 256, 256>>>(w, scale);

    cudaFuncSetAttribute(gemm_kernel, cudaFuncAttributeMaxDynamicSharedMemorySize, SMEM_TOTAL);
    dim3 grid(OUT_DIM / BN, (unsigned)(M / BM));  // (16, 256)
    gemm_kernel<<<grid, THREADS, SMEM_TOTAL>>>((const __nv_bfloat16*)x, bias, d_out);
}